// round 15
// baseline (speedup 1.0000x reference)
#include <cuda_runtime.h>
#include <cuda_fp16.h>
#include <math.h>
#include <stdint.h>

#define SEQ   2048
#define BATCH 2
#define DMODEL 1024
#define NH    16
#define HS    64
#define FF    4096
#define MTOT  (BATCH*SEQ)   /* 4096 rows */

// ---------------- scratch (static device globals; no allocation) ----------------
__device__ __half g_q[MTOT*DMODEL];
__device__ __half g_k[MTOT*DMODEL];
__device__ __half g_v[MTOT*DMODEL];
__device__ __half g_attn[MTOT*DMODEL];
__device__ float  g_y[MTOT*DMODEL];
__device__ float  g_x1[MTOT*DMODEL];
__device__ __half g_x1h[MTOT*DMODEL];
__device__ __half g_h[MTOT*FF];
__device__ float  g_y2[MTOT*DMODEL];
__device__ __half g_xh[MTOT*DMODEL];
__device__ __half g_wqh[DMODEL*DMODEL];
__device__ __half g_wkh[DMODEL*DMODEL];
__device__ __half g_wvh[DMODEL*DMODEL];
__device__ __half g_wph[DMODEL*DMODEL];
__device__ __half g_w1h[(size_t)FF*DMODEL];
__device__ __half g_w2h[(size_t)DMODEL*FF];

__device__ __forceinline__ void mma_f16(float* c, const unsigned* a, const unsigned* b) {
    asm volatile(
        "mma.sync.aligned.m16n8k16.row.col.f32.f16.f16.f32 "
        "{%0,%1,%2,%3},{%4,%5,%6,%7},{%8,%9},{%0,%1,%2,%3};"
        : "+f"(c[0]), "+f"(c[1]), "+f"(c[2]), "+f"(c[3])
        : "r"(a[0]), "r"(a[1]), "r"(a[2]), "r"(a[3]),
          "r"(b[0]), "r"(b[1]));
}
__device__ __forceinline__ void cp16(void* dst, const void* src) {
    unsigned s = (unsigned)__cvta_generic_to_shared(dst);
    asm volatile("cp.async.cg.shared.global [%0], [%1], 16;" :: "r"(s), "l"(src));
}
__device__ __forceinline__ uint32_t s2u(const void* p) {
    return (uint32_t)__cvta_generic_to_shared(p);
}
__device__ __forceinline__ void ldmx4t(unsigned* r, uint32_t addr) {
    asm volatile(
        "ldmatrix.sync.aligned.m8n8.x4.trans.shared.b16 {%0,%1,%2,%3}, [%4];"
        : "=r"(r[0]), "=r"(r[1]), "=r"(r[2]), "=r"(r[3]) : "r"(addr));
}
__device__ __forceinline__ unsigned f2h2u(float a, float b) {
    __half2 h = __floats2half2_rn(a, b);
    return *(unsigned*)&h;
}

// ---------------- pre-pass kernels ----------------------------------------------
__global__ void __launch_bounds__(256)
round_h(const float* __restrict__ src, __half* __restrict__ dst, int n4)
{
    int i = blockIdx.x * 256 + threadIdx.x;
    int stride = gridDim.x * 256;
    for (; i < n4; i += stride) {
        float4 a = ((const float4*)src)[i];
        ((__half2*)dst)[2 * i]     = __floats2half2_rn(a.x, a.y);
        ((__half2*)dst)[2 * i + 1] = __floats2half2_rn(a.z, a.w);
    }
}

__device__ __forceinline__ void
transpose_tile(const float* __restrict__ W, __half* __restrict__ Wt,
               int K, int N, int n0, int k0, size_t bo)
{
    __shared__ float t[32][33];
    const int tx = threadIdx.x & 31, ty = threadIdx.x >> 5;
#pragma unroll
    for (int i = 0; i < 4; i++)
        t[ty + i * 8][tx] = W[bo + (size_t)(k0 + ty + i * 8) * N + n0 + tx];
    __syncthreads();
#pragma unroll
    for (int i = 0; i < 4; i++)
        Wt[bo + (size_t)(n0 + ty + i * 8) * K + k0 + tx] =
            __float2half(t[tx][ty + i * 8]);
}

__global__ void __launch_bounds__(256)
transpose_qkv_h(const float* __restrict__ wq, const float* __restrict__ wk,
                const float* __restrict__ wv,
                __half* __restrict__ wqh, __half* __restrict__ wkh,
                __half* __restrict__ wvh)
{
    int m = blockIdx.z >> 4, head = blockIdx.z & 15;
    const float* W  = (m == 0) ? wq  : (m == 1) ? wk  : wv;
    __half*      Wt = (m == 0) ? wqh : (m == 1) ? wkh : wvh;
    transpose_tile(W, Wt, DMODEL, HS, blockIdx.x * 32, blockIdx.y * 32,
                   (size_t)head * DMODEL * HS);
}

__global__ void __launch_bounds__(256)
transpose3_h(const float* __restrict__ wp, const float* __restrict__ w1,
             const float* __restrict__ w2,
             __half* __restrict__ wph, __half* __restrict__ w1h,
             __half* __restrict__ w2h)
{
    int bid = blockIdx.x;
    if (bid < 1024) {
        transpose_tile(wp, wph, DMODEL, DMODEL, (bid & 31) * 32, (bid >> 5) * 32, 0);
    } else if (bid < 1024 + 4096) {
        int b = bid - 1024;
        transpose_tile(w1, w1h, DMODEL, FF, (b & 127) * 32, (b >> 7) * 32, 0);
    } else {
        int b = bid - 1024 - 4096;
        transpose_tile(w2, w2h, FF, DMODEL, (b & 31) * 32, (b >> 5) * 32, 0);
    }
}

// ---------------- fp16 GEMM: 128x128 tile, 8 warps (2Mx4N) x 64x32 --------------
// 2-stage cp.async, single barrier/iter; 16 warps/SM (2 CTAs).
#define ROWB 144
#define TILE_BYTES (128*ROWB)
#define STG_BYTES  (2*TILE_BYTES)
#define GEMM_SMEM_BYTES (2*STG_BYTES) /* 73728 */

__device__ __forceinline__ void
gemm_core_h(const __half* __restrict__ A, const __half* __restrict__ B,
            const float* __restrict__ bias, void* __restrict__ Cv,
            int K, int ldc, int relu, int halfC, int m0, int n0, char* sm)
{
    const int tid  = threadIdx.x;
    const int warp = tid >> 5, lane = tid & 31;
    const int wm = warp >> 2, wn = warp & 3;     // 2(M) x 4(N)
    const int grp = lane >> 2, thr = lane & 3;
    const int nIter = K >> 6;

    auto prefetch = [&](int it) {
        char* As = sm + (it & 1) * STG_BYTES;
        char* Bs = As + TILE_BYTES;
        const int k0 = it << 6;
#pragma unroll
        for (int i = 0; i < 4; i++) {
            int idx = tid + i * 256;
            int row = idx >> 3, c = idx & 7;
            cp16(As + row * ROWB + c * 16,
                 A + (size_t)(m0 + row) * K + k0 + c * 8);
        }
#pragma unroll
        for (int i = 0; i < 4; i++) {
            int idx = tid + i * 256;
            int row = idx >> 3, c = idx & 7;
            cp16(Bs + row * ROWB + c * 16,
                 B + (size_t)(n0 + row) * K + k0 + c * 8);
        }
        asm volatile("cp.async.commit_group;");
    };

    prefetch(0);

    float acc[4][4][4];
#pragma unroll
    for (int i = 0; i < 4; i++)
#pragma unroll
        for (int j = 0; j < 4; j++)
#pragma unroll
            for (int c = 0; c < 4; c++) acc[i][j][c] = 0.f;

    for (int it = 0; it < nIter; ++it) {
        asm volatile("cp.async.wait_group 0;");
        __syncthreads();
        if (it + 1 < nIter) prefetch(it + 1);

        const char* As = sm + (it & 1) * STG_BYTES;
        const char* Bs = As + TILE_BYTES;

#pragma unroll
        for (int ks = 0; ks < 4; ks++) {
            unsigned a[4][4], b[4][2];
#pragma unroll
            for (int i = 0; i < 4; i++) {
                const char* pa = As + (wm * 64 + i * 16 + grp) * ROWB + ks * 32 + thr * 4;
                a[i][0] = *(const unsigned*)pa;
                a[i][1] = *(const unsigned*)(pa + 8 * ROWB);
                a[i][2] = *(const unsigned*)(pa + 16);
                a[i][3] = *(const unsigned*)(pa + 8 * ROWB + 16);
            }
#pragma unroll
            for (int j = 0; j < 4; j++) {
                const char* pb = Bs + (wn * 32 + j * 8 + grp) * ROWB + ks * 32 + thr * 4;
                b[j][0] = *(const unsigned*)pb;
                b[j][1] = *(const unsigned*)(pb + 16);
            }
#pragma unroll
            for (int i = 0; i < 4; i++)
#pragma unroll
                for (int j = 0; j < 4; j++)
                    mma_f16(acc[i][j], a[i], b[j]);
        }
    }

#pragma unroll
    for (int i = 0; i < 4; i++) {
        int row = m0 + wm * 64 + i * 16 + grp;
#pragma unroll
        for (int j = 0; j < 4; j++) {
            int col = n0 + wn * 32 + j * 8 + thr * 2;
            float v00 = acc[i][j][0], v01 = acc[i][j][1];
            float v10 = acc[i][j][2], v11 = acc[i][j][3];
            if (bias) {
                float2 bv = *(const float2*)(bias + col);
                v00 += bv.x; v01 += bv.y; v10 += bv.x; v11 += bv.y;
            }
            if (relu) {
                v00 = fmaxf(v00, 0.f); v01 = fmaxf(v01, 0.f);
                v10 = fmaxf(v10, 0.f); v11 = fmaxf(v11, 0.f);
            }
            if (halfC) {
                __half* C = (__half*)Cv;
                *(__half2*)(C + (size_t)row * ldc + col)       = __floats2half2_rn(v00, v01);
                *(__half2*)(C + (size_t)(row + 8) * ldc + col) = __floats2half2_rn(v10, v11);
            } else {
                float* C = (float*)Cv;
                *(float2*)(C + (size_t)row * ldc + col)       = make_float2(v00, v01);
                *(float2*)(C + (size_t)(row + 8) * ldc + col) = make_float2(v10, v11);
            }
        }
    }
}

__global__ void __launch_bounds__(256, 2)
gemm_h(const __half* __restrict__ A, const __half* __restrict__ B,
       const float* __restrict__ bias, void* __restrict__ C,
       int K, int ldc, int relu, int halfC)
{
    extern __shared__ char sm[];
    gemm_core_h(A, B, bias, C, K, ldc, relu, halfC,
                blockIdx.y * 128, blockIdx.x * 128, sm);
}

__global__ void __launch_bounds__(256, 2)
gemm_qkv_h(const __half* __restrict__ xh,
           const __half* __restrict__ wqh, const __half* __restrict__ wkh,
           const __half* __restrict__ wvh,
           __half* __restrict__ q, __half* __restrict__ k, __half* __restrict__ v)
{
    extern __shared__ char sm[];
    const __half* B = (blockIdx.z == 0) ? wqh : (blockIdx.z == 1) ? wkh : wvh;
    __half*       C = (blockIdx.z == 0) ? q   : (blockIdx.z == 1) ? k   : v;
    gemm_core_h(xh, B, nullptr, C, DMODEL, DMODEL, 0, 1,
                blockIdx.y * 128, blockIdx.x * 128, sm);
}

// ---------------- causal flash attention, fp16 mma, 2-stage K/V ring ------------
#define ARB 144
#define KV_STAGE (2 * 64 * ARB)
#define ATT_SMEM_BYTES (64 * ARB + 2 * KV_STAGE)    /* 46080 */

__global__ void __launch_bounds__(128)
attn_kernel(const __half* __restrict__ q, const __half* __restrict__ k,
            const __half* __restrict__ v, __half* __restrict__ out)
{
    extern __shared__ char asmem[];
    char* Qs = asmem;

    const int tid  = threadIdx.x;
    const int warp = tid >> 5, lane = tid & 31;
    const int grp = lane >> 2, thr = lane & 3;
    const int t_ = lane >> 3, r_ = lane & 7;
    const int b = blockIdx.z, h = blockIdx.y;
    const int q0 = (gridDim.x - 1 - blockIdx.x) * 64;
    const float SCALE = 0.125f;
    const int nt = q0 / 64 + 1;

    auto prefetch_kv = [&](int kt) {
        char* Ks = asmem + 64 * ARB + (kt & 1) * KV_STAGE;
        char* Vs = Ks + 64 * ARB;
        const int kt0 = kt * 64;
#pragma unroll
        for (int i = 0; i < 4; i++) {
            int idx = tid + i * 128;
            int row = idx >> 3, c = idx & 7;
            cp16(Ks + row * ARB + c * 16,
                 k + (size_t)(b * SEQ + kt0 + row) * DMODEL + h * HS + c * 8);
        }
#pragma unroll
        for (int i = 0; i < 4; i++) {
            int idx = tid + i * 128;
            int row = idx >> 3, c = idx & 7;
            cp16(Vs + row * ARB + c * 16,
                 v + (size_t)(b * SEQ + kt0 + row) * DMODEL + h * HS + c * 8);
        }
        asm volatile("cp.async.commit_group;");
    };

#pragma unroll
    for (int i = 0; i < 4; i++) {
        int idx = tid + i * 128;
        int row = idx >> 3, c = idx & 7;
        cp16(Qs + row * ARB + c * 16,
             q + (size_t)(b * SEQ + q0 + row) * DMODEL + h * HS + c * 8);
    }
    asm volatile("cp.async.commit_group;");
    prefetch_kv(0);
    asm volatile("cp.async.wait_group 1;");
    __syncthreads();

    const int rA = warp * 16 + grp;
    unsigned qf[4][4];
    {
        const char* pa = Qs + rA * ARB;
#pragma unroll
        for (int ks = 0; ks < 4; ks++) {
            qf[ks][0] = *(const unsigned*)(pa + ks * 32 + thr * 4);
            qf[ks][1] = *(const unsigned*)(pa + 8 * ARB + ks * 32 + thr * 4);
            qf[ks][2] = *(const unsigned*)(pa + ks * 32 + 16 + thr * 4);
            qf[ks][3] = *(const unsigned*)(pa + 8 * ARB + ks * 32 + 16 + thr * 4);
        }
    }

    float o[8][4];
#pragma unroll
    for (int j = 0; j < 8; j++)
#pragma unroll
        for (int c = 0; c < 4; c++) o[j][c] = 0.f;
    float m0 = -INFINITY, m1 = -INFINITY, l0 = 0.f, l1 = 0.f;
    const int r0g = q0 + rA, r1g = r0g + 8;

    for (int kt = 0; kt < nt; kt++) {
        const int kt0 = kt * 64;
        asm volatile("cp.async.wait_group 0;");
        __syncthreads();
        if (kt + 1 < nt) prefetch_kv(kt + 1);

        const char* Ks = asmem + 64 * ARB + (kt & 1) * KV_STAGE;
        const char* Vs = Ks + 64 * ARB;

        float s[8][4];
#pragma unroll
        for (int j = 0; j < 8; j++) { s[j][0] = s[j][1] = s[j][2] = s[j][3] = 0.f; }
#pragma unroll
        for (int j = 0; j < 8; j++) {
            const char* pb = Ks + (j * 8 + grp) * ARB;
#pragma unroll
            for (int ks = 0; ks < 4; ks++) {
                unsigned bf[2];
                bf[0] = *(const unsigned*)(pb + ks * 32 + thr * 4);
                bf[1] = *(const unsigned*)(pb + ks * 32 + 16 + thr * 4);
                mma_f16(s[j], qf[ks], bf);
            }
        }

        if (kt == nt - 1) {
#pragma unroll
            for (int j = 0; j < 8; j++) {
                int c0 = kt0 + j * 8 + 2 * thr;
                s[j][0] = (c0     <= r0g) ? s[j][0] * SCALE : -INFINITY;
                s[j][1] = (c0 + 1 <= r0g) ? s[j][1] * SCALE : -INFINITY;
                s[j][2] = (c0     <= r1g) ? s[j][2] * SCALE : -INFINITY;
                s[j][3] = (c0 + 1 <= r1g) ? s[j][3] * SCALE : -INFINITY;
            }
        } else {
#pragma unroll
            for (int j = 0; j < 8; j++) {
                s[j][0] *= SCALE; s[j][1] *= SCALE;
                s[j][2] *= SCALE; s[j][3] *= SCALE;
            }
        }

        float mx0 = -INFINITY, mx1 = -INFINITY;
#pragma unroll
        for (int j = 0; j < 8; j++) {
            mx0 = fmaxf(mx0, fmaxf(s[j][0], s[j][1]));
            mx1 = fmaxf(mx1, fmaxf(s[j][2], s[j][3]));
        }
        mx0 = fmaxf(mx0, __shfl_xor_sync(0xffffffffu, mx0, 1));
        mx0 = fmaxf(mx0, __shfl_xor_sync(0xffffffffu, mx0, 2));
        mx1 = fmaxf(mx1, __shfl_xor_sync(0xffffffffu, mx1, 1));
        mx1 = fmaxf(mx1, __shfl_xor_sync(0xffffffffu, mx1, 2));
        const float mn0 = fmaxf(m0, mx0), mn1 = fmaxf(m1, mx1);
        const float a0 = __expf(m0 - mn0), a1 = __expf(m1 - mn1);
        m0 = mn0; m1 = mn1;

        float ps0 = 0.f, ps1 = 0.f;
#pragma unroll
        for (int j = 0; j < 8; j++) {
            s[j][0] = __expf(s[j][0] - mn0);
            s[j][1] = __expf(s[j][1] - mn0);
            s[j][2] = __expf(s[j][2] - mn1);
            s[j][3] = __expf(s[j][3] - mn1);
            ps0 += s[j][0] + s[j][1];
            ps1 += s[j][2] + s[j][3];
        }
        ps0 += __shfl_xor_sync(0xffffffffu, ps0, 1);
        ps0 += __shfl_xor_sync(0xffffffffu, ps0, 2);
        ps1 += __shfl_xor_sync(0xffffffffu, ps1, 1);
        ps1 += __shfl_xor_sync(0xffffffffu, ps1, 2);
        l0 = l0 * a0 + ps0;
        l1 = l1 * a1 + ps1;

#pragma unroll
        for (int j = 0; j < 8; j++) {
            o[j][0] *= a0; o[j][1] *= a0;
            o[j][2] *= a1; o[j][3] *= a1;
        }

#pragma unroll
        for (int ks = 0; ks < 4; ks++) {
            unsigned pa[4];
            pa[0] = f2h2u(s[2 * ks][0],     s[2 * ks][1]);
            pa[1] = f2h2u(s[2 * ks][2],     s[2 * ks][3]);
            pa[2] = f2h2u(s[2 * ks + 1][0], s[2 * ks + 1][1]);
            pa[3] = f2h2u(s[2 * ks + 1][2], s[2 * ks + 1][3]);
#pragma unroll
            for (int jp = 0; jp < 4; jp++) {
                int jj = 2 * jp + (t_ >> 1), ko = (t_ & 1) * 8;
                uint32_t addr = s2u(Vs + (ks * 16 + ko + r_) * ARB + jj * 16);
                unsigned vb[4];
                ldmx4t(vb, addr);
                mma_f16(o[2 * jp],     pa, vb);
                mma_f16(o[2 * jp + 1], pa, vb + 2);
            }
        }
    }

    const float i0 = 1.f / l0, i1 = 1.f / l1;
    size_t base0 = (size_t)(b * SEQ + r0g) * DMODEL + h * HS;
    size_t base1 = (size_t)(b * SEQ + r1g) * DMODEL + h * HS;
#pragma unroll
    for (int j = 0; j < 8; j++) {
        int col = j * 8 + 2 * thr;
        *(__half2*)(out + base0 + col) = __floats2half2_rn(o[j][0] * i0, o[j][1] * i0);
        *(__half2*)(out + base1 + col) = __floats2half2_rn(o[j][2] * i1, o[j][3] * i1);
    }
}

// ---------------- fused residual + layernorm (one row per block) ----------------
__global__ void __launch_bounds__(256)
add_ln(const float* __restrict__ x, const float* __restrict__ y,
       const float* __restrict__ g, const float* __restrict__ be,
       float* __restrict__ out, __half* __restrict__ out_h)
{
    __shared__ float red[256];
    const int row = blockIdx.x, tid = threadIdx.x;
    const size_t base = (size_t)row * DMODEL;
    float4 xv = ((const float4*)(x + base))[tid];
    float4 yv = ((const float4*)(y + base))[tid];
    float v0 = xv.x + yv.x, v1 = xv.y + yv.y, v2 = xv.z + yv.z, v3 = xv.w + yv.w;

    red[tid] = v0 + v1 + v2 + v3;
    __syncthreads();
    for (int s = 128; s > 0; s >>= 1) {
        if (tid < s) red[tid] += red[tid + s];
        __syncthreads();
    }
    const float mu = red[0] * (1.f / DMODEL);
    __syncthreads();

    float d0 = v0 - mu, d1 = v1 - mu, d2 = v2 - mu, d3 = v3 - mu;
    red[tid] = d0 * d0 + d1 * d1 + d2 * d2 + d3 * d3;
    __syncthreads();
    for (int s = 128; s > 0; s >>= 1) {
        if (tid < s) red[tid] += red[tid + s];
        __syncthreads();
    }
    const float rstd = rsqrtf(red[0] * (1.f / DMODEL) + 1e-5f);

    float4 gv = ((const float4*)g)[tid];
    float4 bv = ((const float4*)be)[tid];
    float4 oo;
    oo.x = d0 * rstd * gv.x + bv.x;
    oo.y = d1 * rstd * gv.y + bv.y;
    oo.z = d2 * rstd * gv.z + bv.z;
    oo.w = d3 * rstd * gv.w + bv.w;
    ((float4*)(out + base))[tid] = oo;
    if (out_h) {
        *(__half2*)(out_h + base + tid * 4)     = __floats2half2_rn(oo.x, oo.y);
        *(__half2*)(out_h + base + tid * 4 + 2) = __floats2half2_rn(oo.z, oo.w);
    }
}

// ---------------- host driver ----------------
extern "C" void kernel_launch(void* const* d_in, const int* in_sizes, int n_in,
                              void* d_out, int out_size)
{
    const float* x      = (const float*)d_in[0];
    const float* wq     = (const float*)d_in[1];
    const float* wk     = (const float*)d_in[2];
    const float* wv     = (const float*)d_in[3];
    const float* w_proj = (const float*)d_in[4];
    const float* b_proj = (const float*)d_in[5];
    const float* w1     = (const float*)d_in[6];
    const float* b1     = (const float*)d_in[7];
    const float* w2     = (const float*)d_in[8];
    const float* b2     = (const float*)d_in[9];
    const float* g1     = (const float*)d_in[10];
    const float* be1    = (const float*)d_in[11];
    const float* g2     = (const float*)d_in[12];
    const float* be2    = (const float*)d_in[13];
    float* out = (float*)d_out;

    float *y, *x1, *y2;
    __half *q, *k, *v, *attn, *x1h, *hbuf, *xh;
    __half *wqh, *wkh, *wvh, *wph, *w1h, *w2h;
    cudaGetSymbolAddress((void**)&q,    g_q);
    cudaGetSymbolAddress((void**)&k,    g_k);
    cudaGetSymbolAddress((void**)&v,    g_v);
    cudaGetSymbolAddress((void**)&attn, g_attn);
    cudaGetSymbolAddress((void**)&y,    g_y);
    cudaGetSymbolAddress((void**)&x1,   g_x1);
    cudaGetSymbolAddress((void**)&x1h,  g_x1h);
    cudaGetSymbolAddress((void**)&hbuf, g_h);
    cudaGetSymbolAddress((void**)&y2,   g_y2);
    cudaGetSymbolAddress((void**)&xh,   g_xh);
    cudaGetSymbolAddress((void**)&wqh,  g_wqh);
    cudaGetSymbolAddress((void**)&wkh,  g_wkh);
    cudaGetSymbolAddress((void**)&wvh,  g_wvh);
    cudaGetSymbolAddress((void**)&wph,  g_wph);
    cudaGetSymbolAddress((void**)&w1h,  g_w1h);
    cudaGetSymbolAddress((void**)&w2h,  g_w2h);

    cudaFuncSetAttribute(attn_kernel,
                         cudaFuncAttributeMaxDynamicSharedMemorySize, ATT_SMEM_BYTES);
    cudaFuncSetAttribute(gemm_h,
                         cudaFuncAttributeMaxDynamicSharedMemorySize, GEMM_SMEM_BYTES);
    cudaFuncSetAttribute(gemm_qkv_h,
                         cudaFuncAttributeMaxDynamicSharedMemorySize, GEMM_SMEM_BYTES);

    dim3 tb(256);

    // ---- pre-pass ----
    transpose_qkv_h<<<dim3(HS/32, DMODEL/32, 3*NH), tb>>>(wq, wk, wv, wqh, wkh, wvh);
    transpose3_h<<<1024 + 4096 + 4096, tb>>>(w_proj, w1, w2, wph, w1h, w2h);
    round_h<<<592, 256>>>(x, xh, MTOT*DMODEL/4);

    // fused QKV (z selects matrix) -> half q,k,v
    dim3 gqkv(DMODEL / 128, MTOT / 128, 3);      // (8, 32, 3)
    gemm_qkv_h<<<gqkv, tb, GEMM_SMEM_BYTES>>>(xh, wqh, wkh, wvh, q, k, v);

    // causal attention (longest-first, pipelined K/V) -> half attn
    dim3 ga(SEQ / 64, NH, BATCH);                // (32, 16, 2)
    attn_kernel<<<ga, dim3(128), ATT_SMEM_BYTES>>>(q, k, v, attn);

    // output projection (fp32 C)
    dim3 gq(DMODEL / 128, MTOT / 128);           // (8, 32)
    gemm_h<<<gq, tb, GEMM_SMEM_BYTES>>>(attn, wph, b_proj, y, DMODEL, DMODEL, 0, 0);

    add_ln<<<MTOT, tb>>>(x, y, g1, be1, x1, x1h);

    dim3 gm1(FF / 128, MTOT / 128);              // (32, 32)
    gemm_h<<<gm1, tb, GEMM_SMEM_BYTES>>>(x1h, w1h, b1, hbuf, DMODEL, FF, 1, 1);
    dim3 gm2(DMODEL / 128, MTOT / 128);          // (8, 32)
    gemm_h<<<gm2, tb, GEMM_SMEM_BYTES>>>(hbuf, w2h, b2, y2, FF, DMODEL, 0, 0);

    add_ln<<<MTOT, tb>>>(x1, y2, g2, be2, out, nullptr);
}

// round 16
// speedup vs baseline: 1.0496x; 1.0496x over previous
#include <cuda_runtime.h>
#include <cuda_fp16.h>
#include <math.h>
#include <stdint.h>

#define SEQ   2048
#define BATCH 2
#define DMODEL 1024
#define NH    16
#define HS    64
#define FF    4096
#define MTOT  (BATCH*SEQ)   /* 4096 rows */

// ---------------- scratch (static device globals; no allocation) ----------------
__device__ __half g_q[MTOT*DMODEL];
__device__ __half g_k[MTOT*DMODEL];
__device__ __half g_v[MTOT*DMODEL];
__device__ __half g_attn[MTOT*DMODEL];
__device__ float  g_y[MTOT*DMODEL];
__device__ float  g_x1[MTOT*DMODEL];
__device__ __half g_x1h[MTOT*DMODEL];
__device__ __half g_h[MTOT*FF];
__device__ float  g_y2[MTOT*DMODEL];
__device__ __half g_xh[MTOT*DMODEL];
__device__ __half g_wqh[DMODEL*DMODEL];
__device__ __half g_wkh[DMODEL*DMODEL];
__device__ __half g_wvh[DMODEL*DMODEL];
__device__ __half g_wph[DMODEL*DMODEL];
__device__ __half g_w1h[(size_t)FF*DMODEL];
__device__ __half g_w2h[(size_t)DMODEL*FF];

__device__ __forceinline__ void mma_f16(float* c, const unsigned* a, const unsigned* b) {
    asm volatile(
        "mma.sync.aligned.m16n8k16.row.col.f32.f16.f16.f32 "
        "{%0,%1,%2,%3},{%4,%5,%6,%7},{%8,%9},{%0,%1,%2,%3};"
        : "+f"(c[0]), "+f"(c[1]), "+f"(c[2]), "+f"(c[3])
        : "r"(a[0]), "r"(a[1]), "r"(a[2]), "r"(a[3]),
          "r"(b[0]), "r"(b[1]));
}
__device__ __forceinline__ void cp16(void* dst, const void* src) {
    unsigned s = (unsigned)__cvta_generic_to_shared(dst);
    asm volatile("cp.async.cg.shared.global [%0], [%1], 16;" :: "r"(s), "l"(src));
}
__device__ __forceinline__ uint32_t s2u(const void* p) {
    return (uint32_t)__cvta_generic_to_shared(p);
}
__device__ __forceinline__ void ldmx4t(unsigned* r, uint32_t addr) {
    asm volatile(
        "ldmatrix.sync.aligned.m8n8.x4.trans.shared.b16 {%0,%1,%2,%3}, [%4];"
        : "=r"(r[0]), "=r"(r[1]), "=r"(r[2]), "=r"(r[3]) : "r"(addr));
}
__device__ __forceinline__ unsigned f2h2u(float a, float b) {
    __half2 h = __floats2half2_rn(a, b);
    return *(unsigned*)&h;
}

// ---------------- fused pre-pass: all weight transposes + x rounding ------------
__device__ __forceinline__ void
transpose_tile(const float* __restrict__ W, __half* __restrict__ Wt,
               int K, int N, int n0, int k0, size_t bo)
{
    __shared__ float t[32][33];
    const int tx = threadIdx.x & 31, ty = threadIdx.x >> 5;
#pragma unroll
    for (int i = 0; i < 4; i++)
        t[ty + i * 8][tx] = W[bo + (size_t)(k0 + ty + i * 8) * N + n0 + tx];
    __syncthreads();
#pragma unroll
    for (int i = 0; i < 4; i++)
        Wt[bo + (size_t)(n0 + ty + i * 8) * K + k0 + tx] =
            __float2half(t[tx][ty + i * 8]);
}

#define PP_QKV   3072   /* 2 x 32 tiles x 48 slabs */
#define PP_PROJ  1024
#define PP_W1    4096
#define PP_W2    4096
#define PP_ROUND 1024
#define PP_TOTAL (PP_QKV + PP_PROJ + PP_W1 + PP_W2 + PP_ROUND)

__global__ void __launch_bounds__(256)
prepass_all(const float* __restrict__ wq, const float* __restrict__ wk,
            const float* __restrict__ wv, const float* __restrict__ wp,
            const float* __restrict__ w1, const float* __restrict__ w2,
            const float* __restrict__ x,
            __half* __restrict__ wqh, __half* __restrict__ wkh,
            __half* __restrict__ wvh, __half* __restrict__ wph,
            __half* __restrict__ w1h, __half* __restrict__ w2h,
            __half* __restrict__ xh)
{
    int bid = blockIdx.x;
    if (bid < PP_QKV) {
        int z = bid >> 6, rem = bid & 63;
        int m = z >> 4, head = z & 15;
        const float* W  = (m == 0) ? wq  : (m == 1) ? wk  : wv;
        __half*      Wt = (m == 0) ? wqh : (m == 1) ? wkh : wvh;
        transpose_tile(W, Wt, DMODEL, HS, (rem & 1) * 32, (rem >> 1) * 32,
                       (size_t)head * DMODEL * HS);
        return;
    }
    bid -= PP_QKV;
    if (bid < PP_PROJ) {
        transpose_tile(wp, wph, DMODEL, DMODEL, (bid & 31) * 32, (bid >> 5) * 32, 0);
        return;
    }
    bid -= PP_PROJ;
    if (bid < PP_W1) {
        transpose_tile(w1, w1h, DMODEL, FF, (bid & 127) * 32, (bid >> 7) * 32, 0);
        return;
    }
    bid -= PP_W1;
    if (bid < PP_W2) {
        transpose_tile(w2, w2h, FF, DMODEL, (bid & 31) * 32, (bid >> 5) * 32, 0);
        return;
    }
    bid -= PP_W2;
    // x rounding: 1M float4s over 1024 blocks
    const int n4 = MTOT * DMODEL / 4;
    int i = bid * 256 + threadIdx.x;
    const int stride = PP_ROUND * 256;
    for (; i < n4; i += stride) {
        float4 a = ((const float4*)x)[i];
        ((__half2*)xh)[2 * i]     = __floats2half2_rn(a.x, a.y);
        ((__half2*)xh)[2 * i + 1] = __floats2half2_rn(a.z, a.w);
    }
}

// ---------------- fp16 GEMM: 128x128 tile, 4 warps x 64x64, 3-stage ring --------
#define ROWB 144
#define TILE_BYTES (128*ROWB)
#define STG_BYTES  (2*TILE_BYTES)
#define GEMM_SMEM_BYTES (3*STG_BYTES) /* 110592 */

__device__ __forceinline__ void
gemm_core_h(const __half* __restrict__ A, const __half* __restrict__ B,
            const float* __restrict__ bias, void* __restrict__ Cv,
            int K, int ldc, int relu, int halfC, int m0, int n0, char* sm)
{
    const int tid  = threadIdx.x;
    const int warp = tid >> 5, lane = tid & 31;
    const int wm = warp >> 1, wn = warp & 1;
    const int grp = lane >> 2, thr = lane & 3;
    const int nIter = K >> 6;

    auto prefetch = [&](int it) {
        char* As = sm + (it % 3) * STG_BYTES;
        char* Bs = As + TILE_BYTES;
        const int k0 = it << 6;
#pragma unroll
        for (int i = 0; i < 8; i++) {
            int idx = tid + i * 128;
            int row = idx >> 3, c = idx & 7;
            cp16(As + row * ROWB + c * 16,
                 A + (size_t)(m0 + row) * K + k0 + c * 8);
        }
#pragma unroll
        for (int i = 0; i < 8; i++) {
            int idx = tid + i * 128;
            int row = idx >> 3, c = idx & 7;
            cp16(Bs + row * ROWB + c * 16,
                 B + (size_t)(n0 + row) * K + k0 + c * 8);
        }
        asm volatile("cp.async.commit_group;");
    };

    prefetch(0);
    if (nIter > 1) prefetch(1);

    float acc[4][8][4];
#pragma unroll
    for (int i = 0; i < 4; i++)
#pragma unroll
        for (int j = 0; j < 8; j++)
#pragma unroll
            for (int c = 0; c < 4; c++) acc[i][j][c] = 0.f;

    for (int it = 0; it < nIter; ++it) {
        if (it + 1 < nIter) asm volatile("cp.async.wait_group 1;");  // group(it) done
        else                asm volatile("cp.async.wait_group 0;");
        __syncthreads();                  // data visible; all warps past compute(it-1)
        if (it + 2 < nIter) prefetch(it + 2);   // buffer (it-1)%3: free post-sync

        const char* As = sm + (it % 3) * STG_BYTES;
        const char* Bs = As + TILE_BYTES;

#pragma unroll
        for (int ks = 0; ks < 4; ks++) {
            unsigned a[4][4], b[8][2];
#pragma unroll
            for (int i = 0; i < 4; i++) {
                const char* pa = As + (wm * 64 + i * 16 + grp) * ROWB + ks * 32 + thr * 4;
                a[i][0] = *(const unsigned*)pa;
                a[i][1] = *(const unsigned*)(pa + 8 * ROWB);
                a[i][2] = *(const unsigned*)(pa + 16);
                a[i][3] = *(const unsigned*)(pa + 8 * ROWB + 16);
            }
#pragma unroll
            for (int j = 0; j < 8; j++) {
                const char* pb = Bs + (wn * 64 + j * 8 + grp) * ROWB + ks * 32 + thr * 4;
                b[j][0] = *(const unsigned*)pb;
                b[j][1] = *(const unsigned*)(pb + 16);
            }
#pragma unroll
            for (int i = 0; i < 4; i++)
#pragma unroll
                for (int j = 0; j < 8; j++)
                    mma_f16(acc[i][j], a[i], b[j]);
        }
    }

#pragma unroll
    for (int i = 0; i < 4; i++) {
        int row = m0 + wm * 64 + i * 16 + grp;
#pragma unroll
        for (int j = 0; j < 8; j++) {
            int col = n0 + wn * 64 + j * 8 + thr * 2;
            float v00 = acc[i][j][0], v01 = acc[i][j][1];
            float v10 = acc[i][j][2], v11 = acc[i][j][3];
            if (bias) {
                float2 bv = *(const float2*)(bias + col);
                v00 += bv.x; v01 += bv.y; v10 += bv.x; v11 += bv.y;
            }
            if (relu) {
                v00 = fmaxf(v00, 0.f); v01 = fmaxf(v01, 0.f);
                v10 = fmaxf(v10, 0.f); v11 = fmaxf(v11, 0.f);
            }
            if (halfC) {
                __half* C = (__half*)Cv;
                *(__half2*)(C + (size_t)row * ldc + col)       = __floats2half2_rn(v00, v01);
                *(__half2*)(C + (size_t)(row + 8) * ldc + col) = __floats2half2_rn(v10, v11);
            } else {
                float* C = (float*)Cv;
                *(float2*)(C + (size_t)row * ldc + col)       = make_float2(v00, v01);
                *(float2*)(C + (size_t)(row + 8) * ldc + col) = make_float2(v10, v11);
            }
        }
    }
}

__global__ void __launch_bounds__(128, 2)
gemm_h(const __half* __restrict__ A, const __half* __restrict__ B,
       const float* __restrict__ bias, void* __restrict__ C,
       int K, int ldc, int relu, int halfC)
{
    extern __shared__ char sm[];
    gemm_core_h(A, B, bias, C, K, ldc, relu, halfC,
                blockIdx.y * 128, blockIdx.x * 128, sm);
}

__global__ void __launch_bounds__(128, 2)
gemm_qkv_h(const __half* __restrict__ xh,
           const __half* __restrict__ wqh, const __half* __restrict__ wkh,
           const __half* __restrict__ wvh,
           __half* __restrict__ q, __half* __restrict__ k, __half* __restrict__ v)
{
    extern __shared__ char sm[];
    const __half* B = (blockIdx.z == 0) ? wqh : (blockIdx.z == 1) ? wkh : wvh;
    __half*       C = (blockIdx.z == 0) ? q   : (blockIdx.z == 1) ? k   : v;
    gemm_core_h(xh, B, nullptr, C, DMODEL, DMODEL, 0, 1,
                blockIdx.y * 128, blockIdx.x * 128, sm);
}

// ---------------- causal flash attention, fp16 mma, 2-stage K/V ring ------------
#define ARB 144
#define KV_STAGE (2 * 64 * ARB)
#define ATT_SMEM_BYTES (64 * ARB + 2 * KV_STAGE)    /* 46080 */

__global__ void __launch_bounds__(128)
attn_kernel(const __half* __restrict__ q, const __half* __restrict__ k,
            const __half* __restrict__ v, __half* __restrict__ out)
{
    extern __shared__ char asmem[];
    char* Qs = asmem;

    const int tid  = threadIdx.x;
    const int warp = tid >> 5, lane = tid & 31;
    const int grp = lane >> 2, thr = lane & 3;
    const int t_ = lane >> 3, r_ = lane & 7;
    const int b = blockIdx.z, h = blockIdx.y;
    const int q0 = (gridDim.x - 1 - blockIdx.x) * 64;
    const float SCALE = 0.125f;
    const int nt = q0 / 64 + 1;

    auto prefetch_kv = [&](int kt) {
        char* Ks = asmem + 64 * ARB + (kt & 1) * KV_STAGE;
        char* Vs = Ks + 64 * ARB;
        const int kt0 = kt * 64;
#pragma unroll
        for (int i = 0; i < 4; i++) {
            int idx = tid + i * 128;
            int row = idx >> 3, c = idx & 7;
            cp16(Ks + row * ARB + c * 16,
                 k + (size_t)(b * SEQ + kt0 + row) * DMODEL + h * HS + c * 8);
        }
#pragma unroll
        for (int i = 0; i < 4; i++) {
            int idx = tid + i * 128;
            int row = idx >> 3, c = idx & 7;
            cp16(Vs + row * ARB + c * 16,
                 v + (size_t)(b * SEQ + kt0 + row) * DMODEL + h * HS + c * 8);
        }
        asm volatile("cp.async.commit_group;");
    };

#pragma unroll
    for (int i = 0; i < 4; i++) {
        int idx = tid + i * 128;
        int row = idx >> 3, c = idx & 7;
        cp16(Qs + row * ARB + c * 16,
             q + (size_t)(b * SEQ + q0 + row) * DMODEL + h * HS + c * 8);
    }
    asm volatile("cp.async.commit_group;");
    prefetch_kv(0);
    asm volatile("cp.async.wait_group 1;");
    __syncthreads();

    const int rA = warp * 16 + grp;
    unsigned qf[4][4];
    {
        const char* pa = Qs + rA * ARB;
#pragma unroll
        for (int ks = 0; ks < 4; ks++) {
            qf[ks][0] = *(const unsigned*)(pa + ks * 32 + thr * 4);
            qf[ks][1] = *(const unsigned*)(pa + 8 * ARB + ks * 32 + thr * 4);
            qf[ks][2] = *(const unsigned*)(pa + ks * 32 + 16 + thr * 4);
            qf[ks][3] = *(const unsigned*)(pa + 8 * ARB + ks * 32 + 16 + thr * 4);
        }
    }

    float o[8][4];
#pragma unroll
    for (int j = 0; j < 8; j++)
#pragma unroll
        for (int c = 0; c < 4; c++) o[j][c] = 0.f;
    float m0 = -INFINITY, m1 = -INFINITY, l0 = 0.f, l1 = 0.f;
    const int r0g = q0 + rA, r1g = r0g + 8;

    for (int kt = 0; kt < nt; kt++) {
        const int kt0 = kt * 64;
        asm volatile("cp.async.wait_group 0;");
        __syncthreads();
        if (kt + 1 < nt) prefetch_kv(kt + 1);

        const char* Ks = asmem + 64 * ARB + (kt & 1) * KV_STAGE;
        const char* Vs = Ks + 64 * ARB;

        float s[8][4];
#pragma unroll
        for (int j = 0; j < 8; j++) { s[j][0] = s[j][1] = s[j][2] = s[j][3] = 0.f; }
#pragma unroll
        for (int j = 0; j < 8; j++) {
            const char* pb = Ks + (j * 8 + grp) * ARB;
#pragma unroll
            for (int ks = 0; ks < 4; ks++) {
                unsigned bf[2];
                bf[0] = *(const unsigned*)(pb + ks * 32 + thr * 4);
                bf[1] = *(const unsigned*)(pb + ks * 32 + 16 + thr * 4);
                mma_f16(s[j], qf[ks], bf);
            }
        }

        if (kt == nt - 1) {
#pragma unroll
            for (int j = 0; j < 8; j++) {
                int c0 = kt0 + j * 8 + 2 * thr;
                s[j][0] = (c0     <= r0g) ? s[j][0] * SCALE : -INFINITY;
                s[j][1] = (c0 + 1 <= r0g) ? s[j][1] * SCALE : -INFINITY;
                s[j][2] = (c0     <= r1g) ? s[j][2] * SCALE : -INFINITY;
                s[j][3] = (c0 + 1 <= r1g) ? s[j][3] * SCALE : -INFINITY;
            }
        } else {
#pragma unroll
            for (int j = 0; j < 8; j++) {
                s[j][0] *= SCALE; s[j][1] *= SCALE;
                s[j][2] *= SCALE; s[j][3] *= SCALE;
            }
        }

        float mx0 = -INFINITY, mx1 = -INFINITY;
#pragma unroll
        for (int j = 0; j < 8; j++) {
            mx0 = fmaxf(mx0, fmaxf(s[j][0], s[j][1]));
            mx1 = fmaxf(mx1, fmaxf(s[j][2], s[j][3]));
        }
        mx0 = fmaxf(mx0, __shfl_xor_sync(0xffffffffu, mx0, 1));
        mx0 = fmaxf(mx0, __shfl_xor_sync(0xffffffffu, mx0, 2));
        mx1 = fmaxf(mx1, __shfl_xor_sync(0xffffffffu, mx1, 1));
        mx1 = fmaxf(mx1, __shfl_xor_sync(0xffffffffu, mx1, 2));
        const float mn0 = fmaxf(m0, mx0), mn1 = fmaxf(m1, mx1);
        const float a0 = __expf(m0 - mn0), a1 = __expf(m1 - mn1);
        m0 = mn0; m1 = mn1;

        float ps0 = 0.f, ps1 = 0.f;
#pragma unroll
        for (int j = 0; j < 8; j++) {
            s[j][0] = __expf(s[j][0] - mn0);
            s[j][1] = __expf(s[j][1] - mn0);
            s[j][2] = __expf(s[j][2] - mn1);
            s[j][3] = __expf(s[j][3] - mn1);
            ps0 += s[j][0] + s[j][1];
            ps1 += s[j][2] + s[j][3];
        }
        ps0 += __shfl_xor_sync(0xffffffffu, ps0, 1);
        ps0 += __shfl_xor_sync(0xffffffffu, ps0, 2);
        ps1 += __shfl_xor_sync(0xffffffffu, ps1, 1);
        ps1 += __shfl_xor_sync(0xffffffffu, ps1, 2);
        l0 = l0 * a0 + ps0;
        l1 = l1 * a1 + ps1;

#pragma unroll
        for (int j = 0; j < 8; j++) {
            o[j][0] *= a0; o[j][1] *= a0;
            o[j][2] *= a1; o[j][3] *= a1;
        }

#pragma unroll
        for (int ks = 0; ks < 4; ks++) {
            unsigned pa[4];
            pa[0] = f2h2u(s[2 * ks][0],     s[2 * ks][1]);
            pa[1] = f2h2u(s[2 * ks][2],     s[2 * ks][3]);
            pa[2] = f2h2u(s[2 * ks + 1][0], s[2 * ks + 1][1]);
            pa[3] = f2h2u(s[2 * ks + 1][2], s[2 * ks + 1][3]);
#pragma unroll
            for (int jp = 0; jp < 4; jp++) {
                int jj = 2 * jp + (t_ >> 1), ko = (t_ & 1) * 8;
                uint32_t addr = s2u(Vs + (ks * 16 + ko + r_) * ARB + jj * 16);
                unsigned vb[4];
                ldmx4t(vb, addr);
                mma_f16(o[2 * jp],     pa, vb);
                mma_f16(o[2 * jp + 1], pa, vb + 2);
            }
        }
    }

    const float i0 = 1.f / l0, i1 = 1.f / l1;
    size_t base0 = (size_t)(b * SEQ + r0g) * DMODEL + h * HS;
    size_t base1 = (size_t)(b * SEQ + r1g) * DMODEL + h * HS;
#pragma unroll
    for (int j = 0; j < 8; j++) {
        int col = j * 8 + 2 * thr;
        *(__half2*)(out + base0 + col) = __floats2half2_rn(o[j][0] * i0, o[j][1] * i0);
        *(__half2*)(out + base1 + col) = __floats2half2_rn(o[j][2] * i1, o[j][3] * i1);
    }
}

// ---------------- fused residual + layernorm (one-pass sum/sumsq) ---------------
__global__ void __launch_bounds__(256)
add_ln(const float* __restrict__ x, const float* __restrict__ y,
       const float* __restrict__ g, const float* __restrict__ be,
       float* __restrict__ out, __half* __restrict__ out_h)
{
    __shared__ float2 red[8];
    const int row = blockIdx.x, tid = threadIdx.x;
    const int lane = tid & 31, warp = tid >> 5;
    const size_t base = (size_t)row * DMODEL;
    float4 xv = ((const float4*)(x + base))[tid];
    float4 yv = ((const float4*)(y + base))[tid];
    float v0 = xv.x + yv.x, v1 = xv.y + yv.y, v2 = xv.z + yv.z, v3 = xv.w + yv.w;

    float s1 = v0 + v1 + v2 + v3;
    float s2 = v0 * v0 + v1 * v1 + v2 * v2 + v3 * v3;
#pragma unroll
    for (int o = 16; o; o >>= 1) {
        s1 += __shfl_xor_sync(0xffffffffu, s1, o);
        s2 += __shfl_xor_sync(0xffffffffu, s2, o);
    }
    if (lane == 0) red[warp] = make_float2(s1, s2);
    __syncthreads();
    if (warp == 0) {
        float2 r = (lane < 8) ? red[lane] : make_float2(0.f, 0.f);
        float a = r.x, bb = r.y;
#pragma unroll
        for (int o = 4; o; o >>= 1) {
            a  += __shfl_xor_sync(0xffffffffu, a, o);
            bb += __shfl_xor_sync(0xffffffffu, bb, o);
        }
        if (lane == 0) red[0] = make_float2(a, bb);
    }
    __syncthreads();
    const float mu   = red[0].x * (1.f / DMODEL);
    const float var  = red[0].y * (1.f / DMODEL) - mu * mu;
    const float rstd = rsqrtf(var + 1e-5f);

    float4 gv = ((const float4*)g)[tid];
    float4 bv = ((const float4*)be)[tid];
    float4 oo;
    oo.x = (v0 - mu) * rstd * gv.x + bv.x;
    oo.y = (v1 - mu) * rstd * gv.y + bv.y;
    oo.z = (v2 - mu) * rstd * gv.z + bv.z;
    oo.w = (v3 - mu) * rstd * gv.w + bv.w;
    ((float4*)(out + base))[tid] = oo;
    if (out_h) {
        *(__half2*)(out_h + base + tid * 4)     = __floats2half2_rn(oo.x, oo.y);
        *(__half2*)(out_h + base + tid * 4 + 2) = __floats2half2_rn(oo.z, oo.w);
    }
}

// ---------------- host driver ----------------
extern "C" void kernel_launch(void* const* d_in, const int* in_sizes, int n_in,
                              void* d_out, int out_size)
{
    const float* x      = (const float*)d_in[0];
    const float* wq     = (const float*)d_in[1];
    const float* wk     = (const float*)d_in[2];
    const float* wv     = (const float*)d_in[3];
    const float* w_proj = (const float*)d_in[4];
    const float* b_proj = (const float*)d_in[5];
    const float* w1     = (const float*)d_in[6];
    const float* b1     = (const float*)d_in[7];
    const float* w2     = (const float*)d_in[8];
    const float* b2     = (const float*)d_in[9];
    const float* g1     = (const float*)d_in[10];
    const float* be1    = (const float*)d_in[11];
    const float* g2     = (const float*)d_in[12];
    const float* be2    = (const float*)d_in[13];
    float* out = (float*)d_out;

    float *y, *x1, *y2;
    __half *q, *k, *v, *attn, *x1h, *hbuf, *xh;
    __half *wqh, *wkh, *wvh, *wph, *w1h, *w2h;
    cudaGetSymbolAddress((void**)&q,    g_q);
    cudaGetSymbolAddress((void**)&k,    g_k);
    cudaGetSymbolAddress((void**)&v,    g_v);
    cudaGetSymbolAddress((void**)&attn, g_attn);
    cudaGetSymbolAddress((void**)&y,    g_y);
    cudaGetSymbolAddress((void**)&x1,   g_x1);
    cudaGetSymbolAddress((void**)&x1h,  g_x1h);
    cudaGetSymbolAddress((void**)&hbuf, g_h);
    cudaGetSymbolAddress((void**)&y2,   g_y2);
    cudaGetSymbolAddress((void**)&xh,   g_xh);
    cudaGetSymbolAddress((void**)&wqh,  g_wqh);
    cudaGetSymbolAddress((void**)&wkh,  g_wkh);
    cudaGetSymbolAddress((void**)&wvh,  g_wvh);
    cudaGetSymbolAddress((void**)&wph,  g_wph);
    cudaGetSymbolAddress((void**)&w1h,  g_w1h);
    cudaGetSymbolAddress((void**)&w2h,  g_w2h);

    cudaFuncSetAttribute(attn_kernel,
                         cudaFuncAttributeMaxDynamicSharedMemorySize, ATT_SMEM_BYTES);
    cudaFuncSetAttribute(gemm_h,
                         cudaFuncAttributeMaxDynamicSharedMemorySize, GEMM_SMEM_BYTES);
    cudaFuncSetAttribute(gemm_qkv_h,
                         cudaFuncAttributeMaxDynamicSharedMemorySize, GEMM_SMEM_BYTES);

    dim3 tb(256);
    dim3 gb(128);

    // ---- fused pre-pass (single launch) ----
    prepass_all<<<PP_TOTAL, tb>>>(wq, wk, wv, w_proj, w1, w2, x,
                                  wqh, wkh, wvh, wph, w1h, w2h, xh);

    // fused QKV (z selects matrix) -> half q,k,v
    dim3 gqkv(DMODEL / 128, MTOT / 128, 3);      // (8, 32, 3)
    gemm_qkv_h<<<gqkv, gb, GEMM_SMEM_BYTES>>>(xh, wqh, wkh, wvh, q, k, v);

    // causal attention (longest-first, pipelined K/V) -> half attn
    dim3 ga(SEQ / 64, NH, BATCH);                // (32, 16, 2)
    attn_kernel<<<ga, dim3(128), ATT_SMEM_BYTES>>>(q, k, v, attn);

    // output projection (fp32 C)
    dim3 gq(DMODEL / 128, MTOT / 128);           // (8, 32)
    gemm_h<<<gq, gb, GEMM_SMEM_BYTES>>>(attn, wph, b_proj, y, DMODEL, DMODEL, 0, 0);

    add_ln<<<MTOT, tb>>>(x, y, g1, be1, x1, x1h);

    dim3 gm1(FF / 128, MTOT / 128);              // (32, 32)
    gemm_h<<<gm1, gb, GEMM_SMEM_BYTES>>>(x1h, w1h, b1, hbuf, DMODEL, FF, 1, 1);
    dim3 gm2(DMODEL / 128, MTOT / 128);          // (8, 32)
    gemm_h<<<gm2, gb, GEMM_SMEM_BYTES>>>(hbuf, w2h, b2, y2, FF, DMODEL, 0, 0);

    add_ln<<<MTOT, tb>>>(x1, y2, g2, be2, out, nullptr);
}

// round 17
// speedup vs baseline: 1.1088x; 1.0563x over previous
#include <cuda_runtime.h>
#include <cuda_fp16.h>
#include <math.h>
#include <stdint.h>

#define SEQ   2048
#define BATCH 2
#define DMODEL 1024
#define NH    16
#define HS    64
#define FF    4096
#define MTOT  (BATCH*SEQ)   /* 4096 rows */

// ---------------- scratch (static device globals; no allocation) ----------------
__device__ __half g_q[MTOT*DMODEL];
__device__ __half g_k[MTOT*DMODEL];
__device__ __half g_v[MTOT*DMODEL];
__device__ __half g_attn[MTOT*DMODEL];
__device__ float  g_y[MTOT*DMODEL];
__device__ float  g_x1[MTOT*DMODEL];
__device__ __half g_x1h[MTOT*DMODEL];
__device__ __half g_h[MTOT*FF];
__device__ float  g_y2[MTOT*DMODEL];
__device__ __half g_xh[MTOT*DMODEL];
__device__ __half g_wqh[DMODEL*DMODEL];
__device__ __half g_wkh[DMODEL*DMODEL];
__device__ __half g_wvh[DMODEL*DMODEL];
__device__ __half g_wph[DMODEL*DMODEL];
__device__ __half g_w1h[(size_t)FF*DMODEL];
__device__ __half g_w2h[(size_t)DMODEL*FF];

__device__ __forceinline__ void mma_f16(float* c, const unsigned* a, const unsigned* b) {
    asm volatile(
        "mma.sync.aligned.m16n8k16.row.col.f32.f16.f16.f32 "
        "{%0,%1,%2,%3},{%4,%5,%6,%7},{%8,%9},{%0,%1,%2,%3};"
        : "+f"(c[0]), "+f"(c[1]), "+f"(c[2]), "+f"(c[3])
        : "r"(a[0]), "r"(a[1]), "r"(a[2]), "r"(a[3]),
          "r"(b[0]), "r"(b[1]));
}
__device__ __forceinline__ void cp16(void* dst, const void* src) {
    unsigned s = (unsigned)__cvta_generic_to_shared(dst);
    asm volatile("cp.async.cg.shared.global [%0], [%1], 16;" :: "r"(s), "l"(src));
}
__device__ __forceinline__ uint32_t s2u(const void* p) {
    return (uint32_t)__cvta_generic_to_shared(p);
}
__device__ __forceinline__ void ldmx4t(unsigned* r, uint32_t addr) {
    asm volatile(
        "ldmatrix.sync.aligned.m8n8.x4.trans.shared.b16 {%0,%1,%2,%3}, [%4];"
        : "=r"(r[0]), "=r"(r[1]), "=r"(r[2]), "=r"(r[3]) : "r"(addr));
}
__device__ __forceinline__ unsigned f2h2u(float a, float b) {
    __half2 h = __floats2half2_rn(a, b);
    return *(unsigned*)&h;
}

// ---------------- fused pre-pass: all weight transposes + x rounding ------------
__device__ __forceinline__ void
transpose_tile(const float* __restrict__ W, __half* __restrict__ Wt,
               int K, int N, int n0, int k0, size_t bo)
{
    __shared__ float t[32][33];
    const int tx = threadIdx.x & 31, ty = threadIdx.x >> 5;
#pragma unroll
    for (int i = 0; i < 4; i++)
        t[ty + i * 8][tx] = W[bo + (size_t)(k0 + ty + i * 8) * N + n0 + tx];
    __syncthreads();
#pragma unroll
    for (int i = 0; i < 4; i++)
        Wt[bo + (size_t)(n0 + ty + i * 8) * K + k0 + tx] =
            __float2half(t[tx][ty + i * 8]);
}

#define PP_QKV   3072
#define PP_PROJ  1024
#define PP_W1    4096
#define PP_W2    4096
#define PP_ROUND 1024
#define PP_TOTAL (PP_QKV + PP_PROJ + PP_W1 + PP_W2 + PP_ROUND)

__global__ void __launch_bounds__(256)
prepass_all(const float* __restrict__ wq, const float* __restrict__ wk,
            const float* __restrict__ wv, const float* __restrict__ wp,
            const float* __restrict__ w1, const float* __restrict__ w2,
            const float* __restrict__ x,
            __half* __restrict__ wqh, __half* __restrict__ wkh,
            __half* __restrict__ wvh, __half* __restrict__ wph,
            __half* __restrict__ w1h, __half* __restrict__ w2h,
            __half* __restrict__ xh)
{
    int bid = blockIdx.x;
    if (bid < PP_QKV) {
        int z = bid >> 6, rem = bid & 63;
        int m = z >> 4, head = z & 15;
        const float* W  = (m == 0) ? wq  : (m == 1) ? wk  : wv;
        __half*      Wt = (m == 0) ? wqh : (m == 1) ? wkh : wvh;
        transpose_tile(W, Wt, DMODEL, HS, (rem & 1) * 32, (rem >> 1) * 32,
                       (size_t)head * DMODEL * HS);
        return;
    }
    bid -= PP_QKV;
    if (bid < PP_PROJ) {
        transpose_tile(wp, wph, DMODEL, DMODEL, (bid & 31) * 32, (bid >> 5) * 32, 0);
        return;
    }
    bid -= PP_PROJ;
    if (bid < PP_W1) {
        transpose_tile(w1, w1h, DMODEL, FF, (bid & 127) * 32, (bid >> 7) * 32, 0);
        return;
    }
    bid -= PP_W1;
    if (bid < PP_W2) {
        transpose_tile(w2, w2h, FF, DMODEL, (bid & 31) * 32, (bid >> 5) * 32, 0);
        return;
    }
    bid -= PP_W2;
    const int n4 = MTOT * DMODEL / 4;
    int i = bid * 256 + threadIdx.x;
    const int stride = PP_ROUND * 256;
    for (; i < n4; i += stride) {
        float4 a = ((const float4*)x)[i];
        ((__half2*)xh)[2 * i]     = __floats2half2_rn(a.x, a.y);
        ((__half2*)xh)[2 * i + 1] = __floats2half2_rn(a.z, a.w);
    }
}

// ---------------- fp16 GEMM: 128x128 tile, 4 warps x 64x64, 2-stage, 1 barrier --
#define ROWB 144
#define TILE_BYTES (128*ROWB)
#define STG_BYTES  (2*TILE_BYTES)
#define GEMM_SMEM_BYTES (2*STG_BYTES) /* 73728 */

__device__ __forceinline__ void
gemm_core_h(const __half* __restrict__ A, const __half* __restrict__ B,
            const float* __restrict__ bias, void* __restrict__ Cv,
            int K, int ldc, int relu, int halfC, int m0, int n0, char* sm)
{
    const int tid  = threadIdx.x;
    const int warp = tid >> 5, lane = tid & 31;
    const int wm = warp >> 1, wn = warp & 1;
    const int grp = lane >> 2, thr = lane & 3;
    const int nIter = K >> 6;

    auto prefetch = [&](int it) {
        char* As = sm + (it & 1) * STG_BYTES;
        char* Bs = As + TILE_BYTES;
        const int k0 = it << 6;
#pragma unroll
        for (int i = 0; i < 8; i++) {
            int idx = tid + i * 128;
            int row = idx >> 3, c = idx & 7;
            cp16(As + row * ROWB + c * 16,
                 A + (size_t)(m0 + row) * K + k0 + c * 8);
        }
#pragma unroll
        for (int i = 0; i < 8; i++) {
            int idx = tid + i * 128;
            int row = idx >> 3, c = idx & 7;
            cp16(Bs + row * ROWB + c * 16,
                 B + (size_t)(n0 + row) * K + k0 + c * 8);
        }
        asm volatile("cp.async.commit_group;");
    };

    prefetch(0);

    float acc[4][8][4];
#pragma unroll
    for (int i = 0; i < 4; i++)
#pragma unroll
        for (int j = 0; j < 8; j++)
#pragma unroll
            for (int c = 0; c < 4; c++) acc[i][j][c] = 0.f;

    for (int it = 0; it < nIter; ++it) {
        asm volatile("cp.async.wait_group 0;");   // prefetch(it) complete
        __syncthreads();                          // visible; all warps past compute(it-1)
        if (it + 1 < nIter) prefetch(it + 1);     // overlaps compute(it)

        const char* As = sm + (it & 1) * STG_BYTES;
        const char* Bs = As + TILE_BYTES;

#pragma unroll
        for (int ks = 0; ks < 4; ks++) {
            unsigned a[4][4], b[8][2];
#pragma unroll
            for (int i = 0; i < 4; i++) {
                const char* pa = As + (wm * 64 + i * 16 + grp) * ROWB + ks * 32 + thr * 4;
                a[i][0] = *(const unsigned*)pa;
                a[i][1] = *(const unsigned*)(pa + 8 * ROWB);
                a[i][2] = *(const unsigned*)(pa + 16);
                a[i][3] = *(const unsigned*)(pa + 8 * ROWB + 16);
            }
#pragma unroll
            for (int j = 0; j < 8; j++) {
                const char* pb = Bs + (wn * 64 + j * 8 + grp) * ROWB + ks * 32 + thr * 4;
                b[j][0] = *(const unsigned*)pb;
                b[j][1] = *(const unsigned*)(pb + 16);
            }
#pragma unroll
            for (int i = 0; i < 4; i++)
#pragma unroll
                for (int j = 0; j < 8; j++)
                    mma_f16(acc[i][j], a[i], b[j]);
        }
    }

#pragma unroll
    for (int i = 0; i < 4; i++) {
        int row = m0 + wm * 64 + i * 16 + grp;
#pragma unroll
        for (int j = 0; j < 8; j++) {
            int col = n0 + wn * 64 + j * 8 + thr * 2;
            float v00 = acc[i][j][0], v01 = acc[i][j][1];
            float v10 = acc[i][j][2], v11 = acc[i][j][3];
            if (bias) {
                float2 bv = *(const float2*)(bias + col);
                v00 += bv.x; v01 += bv.y; v10 += bv.x; v11 += bv.y;
            }
            if (relu) {
                v00 = fmaxf(v00, 0.f); v01 = fmaxf(v01, 0.f);
                v10 = fmaxf(v10, 0.f); v11 = fmaxf(v11, 0.f);
            }
            if (halfC) {
                __half* C = (__half*)Cv;
                *(__half2*)(C + (size_t)row * ldc + col)       = __floats2half2_rn(v00, v01);
                *(__half2*)(C + (size_t)(row + 8) * ldc + col) = __floats2half2_rn(v10, v11);
            } else {
                float* C = (float*)Cv;
                *(float2*)(C + (size_t)row * ldc + col)       = make_float2(v00, v01);
                *(float2*)(C + (size_t)(row + 8) * ldc + col) = make_float2(v10, v11);
            }
        }
    }
}

__global__ void __launch_bounds__(128, 2)
gemm_h(const __half* __restrict__ A, const __half* __restrict__ B,
       const float* __restrict__ bias, void* __restrict__ C,
       int K, int ldc, int relu, int halfC)
{
    extern __shared__ char sm[];
    gemm_core_h(A, B, bias, C, K, ldc, relu, halfC,
                blockIdx.y * 128, blockIdx.x * 128, sm);
}

__global__ void __launch_bounds__(128, 2)
gemm_qkv_h(const __half* __restrict__ xh,
           const __half* __restrict__ wqh, const __half* __restrict__ wkh,
           const __half* __restrict__ wvh,
           __half* __restrict__ q, __half* __restrict__ k, __half* __restrict__ v)
{
    extern __shared__ char sm[];
    const __half* B = (blockIdx.z == 0) ? wqh : (blockIdx.z == 1) ? wkh : wvh;
    __half*       C = (blockIdx.z == 0) ? q   : (blockIdx.z == 1) ? k   : v;
    gemm_core_h(xh, B, nullptr, C, DMODEL, DMODEL, 0, 1,
                blockIdx.y * 128, blockIdx.x * 128, sm);
}

// ---------------- causal flash attention, fp16 mma, 2-stage K/V ring ------------
#define ARB 144
#define KV_STAGE (2 * 64 * ARB)
#define ATT_SMEM_BYTES (64 * ARB + 2 * KV_STAGE)    /* 46080 */

__global__ void __launch_bounds__(128)
attn_kernel(const __half* __restrict__ q, const __half* __restrict__ k,
            const __half* __restrict__ v, __half* __restrict__ out)
{
    extern __shared__ char asmem[];
    char* Qs = asmem;

    const int tid  = threadIdx.x;
    const int warp = tid >> 5, lane = tid & 31;
    const int grp = lane >> 2, thr = lane & 3;
    const int t_ = lane >> 3, r_ = lane & 7;
    const int b = blockIdx.z, h = blockIdx.y;
    const int q0 = (gridDim.x - 1 - blockIdx.x) * 64;
    const float SCALE = 0.125f;
    const int nt = q0 / 64 + 1;

    auto prefetch_kv = [&](int kt) {
        char* Ks = asmem + 64 * ARB + (kt & 1) * KV_STAGE;
        char* Vs = Ks + 64 * ARB;
        const int kt0 = kt * 64;
#pragma unroll
        for (int i = 0; i < 4; i++) {
            int idx = tid + i * 128;
            int row = idx >> 3, c = idx & 7;
            cp16(Ks + row * ARB + c * 16,
                 k + (size_t)(b * SEQ + kt0 + row) * DMODEL + h * HS + c * 8);
        }
#pragma unroll
        for (int i = 0; i < 4; i++) {
            int idx = tid + i * 128;
            int row = idx >> 3, c = idx & 7;
            cp16(Vs + row * ARB + c * 16,
                 v + (size_t)(b * SEQ + kt0 + row) * DMODEL + h * HS + c * 8);
        }
        asm volatile("cp.async.commit_group;");
    };

#pragma unroll
    for (int i = 0; i < 4; i++) {
        int idx = tid + i * 128;
        int row = idx >> 3, c = idx & 7;
        cp16(Qs + row * ARB + c * 16,
             q + (size_t)(b * SEQ + q0 + row) * DMODEL + h * HS + c * 8);
    }
    asm volatile("cp.async.commit_group;");
    prefetch_kv(0);
    asm volatile("cp.async.wait_group 1;");
    __syncthreads();

    const int rA = warp * 16 + grp;
    unsigned qf[4][4];
    {
        const char* pa = Qs + rA * ARB;
#pragma unroll
        for (int ks = 0; ks < 4; ks++) {
            qf[ks][0] = *(const unsigned*)(pa + ks * 32 + thr * 4);
            qf[ks][1] = *(const unsigned*)(pa + 8 * ARB + ks * 32 + thr * 4);
            qf[ks][2] = *(const unsigned*)(pa + ks * 32 + 16 + thr * 4);
            qf[ks][3] = *(const unsigned*)(pa + 8 * ARB + ks * 32 + 16 + thr * 4);
        }
    }

    float o[8][4];
#pragma unroll
    for (int j = 0; j < 8; j++)
#pragma unroll
        for (int c = 0; c < 4; c++) o[j][c] = 0.f;
    float m0 = -INFINITY, m1 = -INFINITY, l0 = 0.f, l1 = 0.f;
    const int r0g = q0 + rA, r1g = r0g + 8;

    for (int kt = 0; kt < nt; kt++) {
        const int kt0 = kt * 64;
        asm volatile("cp.async.wait_group 0;");
        __syncthreads();
        if (kt + 1 < nt) prefetch_kv(kt + 1);

        const char* Ks = asmem + 64 * ARB + (kt & 1) * KV_STAGE;
        const char* Vs = Ks + 64 * ARB;

        float s[8][4];
#pragma unroll
        for (int j = 0; j < 8; j++) { s[j][0] = s[j][1] = s[j][2] = s[j][3] = 0.f; }
#pragma unroll
        for (int j = 0; j < 8; j++) {
            const char* pb = Ks + (j * 8 + grp) * ARB;
#pragma unroll
            for (int ks = 0; ks < 4; ks++) {
                unsigned bf[2];
                bf[0] = *(const unsigned*)(pb + ks * 32 + thr * 4);
                bf[1] = *(const unsigned*)(pb + ks * 32 + 16 + thr * 4);
                mma_f16(s[j], qf[ks], bf);
            }
        }

        if (kt == nt - 1) {
#pragma unroll
            for (int j = 0; j < 8; j++) {
                int c0 = kt0 + j * 8 + 2 * thr;
                s[j][0] = (c0     <= r0g) ? s[j][0] * SCALE : -INFINITY;
                s[j][1] = (c0 + 1 <= r0g) ? s[j][1] * SCALE : -INFINITY;
                s[j][2] = (c0     <= r1g) ? s[j][2] * SCALE : -INFINITY;
                s[j][3] = (c0 + 1 <= r1g) ? s[j][3] * SCALE : -INFINITY;
            }
        } else {
#pragma unroll
            for (int j = 0; j < 8; j++) {
                s[j][0] *= SCALE; s[j][1] *= SCALE;
                s[j][2] *= SCALE; s[j][3] *= SCALE;
            }
        }

        float mx0 = -INFINITY, mx1 = -INFINITY;
#pragma unroll
        for (int j = 0; j < 8; j++) {
            mx0 = fmaxf(mx0, fmaxf(s[j][0], s[j][1]));
            mx1 = fmaxf(mx1, fmaxf(s[j][2], s[j][3]));
        }
        mx0 = fmaxf(mx0, __shfl_xor_sync(0xffffffffu, mx0, 1));
        mx0 = fmaxf(mx0, __shfl_xor_sync(0xffffffffu, mx0, 2));
        mx1 = fmaxf(mx1, __shfl_xor_sync(0xffffffffu, mx1, 1));
        mx1 = fmaxf(mx1, __shfl_xor_sync(0xffffffffu, mx1, 2));
        const float mn0 = fmaxf(m0, mx0), mn1 = fmaxf(m1, mx1);
        const float a0 = __expf(m0 - mn0), a1 = __expf(m1 - mn1);
        m0 = mn0; m1 = mn1;

        float ps0 = 0.f, ps1 = 0.f;
#pragma unroll
        for (int j = 0; j < 8; j++) {
            s[j][0] = __expf(s[j][0] - mn0);
            s[j][1] = __expf(s[j][1] - mn0);
            s[j][2] = __expf(s[j][2] - mn1);
            s[j][3] = __expf(s[j][3] - mn1);
            ps0 += s[j][0] + s[j][1];
            ps1 += s[j][2] + s[j][3];
        }
        ps0 += __shfl_xor_sync(0xffffffffu, ps0, 1);
        ps0 += __shfl_xor_sync(0xffffffffu, ps0, 2);
        ps1 += __shfl_xor_sync(0xffffffffu, ps1, 1);
        ps1 += __shfl_xor_sync(0xffffffffu, ps1, 2);
        l0 = l0 * a0 + ps0;
        l1 = l1 * a1 + ps1;

#pragma unroll
        for (int j = 0; j < 8; j++) {
            o[j][0] *= a0; o[j][1] *= a0;
            o[j][2] *= a1; o[j][3] *= a1;
        }

#pragma unroll
        for (int ks = 0; ks < 4; ks++) {
            unsigned pa[4];
            pa[0] = f2h2u(s[2 * ks][0],     s[2 * ks][1]);
            pa[1] = f2h2u(s[2 * ks][2],     s[2 * ks][3]);
            pa[2] = f2h2u(s[2 * ks + 1][0], s[2 * ks + 1][1]);
            pa[3] = f2h2u(s[2 * ks + 1][2], s[2 * ks + 1][3]);
#pragma unroll
            for (int jp = 0; jp < 4; jp++) {
                int jj = 2 * jp + (t_ >> 1), ko = (t_ & 1) * 8;
                uint32_t addr = s2u(Vs + (ks * 16 + ko + r_) * ARB + jj * 16);
                unsigned vb[4];
                ldmx4t(vb, addr);
                mma_f16(o[2 * jp],     pa, vb);
                mma_f16(o[2 * jp + 1], pa, vb + 2);
            }
        }
    }

    const float i0 = 1.f / l0, i1 = 1.f / l1;
    size_t base0 = (size_t)(b * SEQ + r0g) * DMODEL + h * HS;
    size_t base1 = (size_t)(b * SEQ + r1g) * DMODEL + h * HS;
#pragma unroll
    for (int j = 0; j < 8; j++) {
        int col = j * 8 + 2 * thr;
        *(__half2*)(out + base0 + col) = __floats2half2_rn(o[j][0] * i0, o[j][1] * i0);
        *(__half2*)(out + base1 + col) = __floats2half2_rn(o[j][2] * i1, o[j][3] * i1);
    }
}

// ---------------- fused residual + layernorm (one-pass sum/sumsq) ---------------
__global__ void __launch_bounds__(256)
add_ln(const float* __restrict__ x, const float* __restrict__ y,
       const float* __restrict__ g, const float* __restrict__ be,
       float* __restrict__ out, __half* __restrict__ out_h)
{
    __shared__ float2 red[8];
    const int row = blockIdx.x, tid = threadIdx.x;
    const int lane = tid & 31, warp = tid >> 5;
    const size_t base = (size_t)row * DMODEL;
    float4 xv = ((const float4*)(x + base))[tid];
    float4 yv = ((const float4*)(y + base))[tid];
    float v0 = xv.x + yv.x, v1 = xv.y + yv.y, v2 = xv.z + yv.z, v3 = xv.w + yv.w;

    float s1 = v0 + v1 + v2 + v3;
    float s2 = v0 * v0 + v1 * v1 + v2 * v2 + v3 * v3;
#pragma unroll
    for (int o = 16; o; o >>= 1) {
        s1 += __shfl_xor_sync(0xffffffffu, s1, o);
        s2 += __shfl_xor_sync(0xffffffffu, s2, o);
    }
    if (lane == 0) red[warp] = make_float2(s1, s2);
    __syncthreads();
    if (warp == 0) {
        float2 r = (lane < 8) ? red[lane] : make_float2(0.f, 0.f);
        float a = r.x, bb = r.y;
#pragma unroll
        for (int o = 4; o; o >>= 1) {
            a  += __shfl_xor_sync(0xffffffffu, a, o);
            bb += __shfl_xor_sync(0xffffffffu, bb, o);
        }
        if (lane == 0) red[0] = make_float2(a, bb);
    }
    __syncthreads();
    const float mu   = red[0].x * (1.f / DMODEL);
    const float var  = red[0].y * (1.f / DMODEL) - mu * mu;
    const float rstd = rsqrtf(var + 1e-5f);

    float4 gv = ((const float4*)g)[tid];
    float4 bv = ((const float4*)be)[tid];
    float4 oo;
    oo.x = (v0 - mu) * rstd * gv.x + bv.x;
    oo.y = (v1 - mu) * rstd * gv.y + bv.y;
    oo.z = (v2 - mu) * rstd * gv.z + bv.z;
    oo.w = (v3 - mu) * rstd * gv.w + bv.w;
    ((float4*)(out + base))[tid] = oo;
    if (out_h) {
        *(__half2*)(out_h + base + tid * 4)     = __floats2half2_rn(oo.x, oo.y);
        *(__half2*)(out_h + base + tid * 4 + 2) = __floats2half2_rn(oo.z, oo.w);
    }
}

// ---------------- host driver ----------------
extern "C" void kernel_launch(void* const* d_in, const int* in_sizes, int n_in,
                              void* d_out, int out_size)
{
    const float* x      = (const float*)d_in[0];
    const float* wq     = (const float*)d_in[1];
    const float* wk     = (const float*)d_in[2];
    const float* wv     = (const float*)d_in[3];
    const float* w_proj = (const float*)d_in[4];
    const float* b_proj = (const float*)d_in[5];
    const float* w1     = (const float*)d_in[6];
    const float* b1     = (const float*)d_in[7];
    const float* w2     = (const float*)d_in[8];
    const float* b2     = (const float*)d_in[9];
    const float* g1     = (const float*)d_in[10];
    const float* be1    = (const float*)d_in[11];
    const float* g2     = (const float*)d_in[12];
    const float* be2    = (const float*)d_in[13];
    float* out = (float*)d_out;

    float *y, *x1, *y2;
    __half *q, *k, *v, *attn, *x1h, *hbuf, *xh;
    __half *wqh, *wkh, *wvh, *wph, *w1h, *w2h;
    cudaGetSymbolAddress((void**)&q,    g_q);
    cudaGetSymbolAddress((void**)&k,    g_k);
    cudaGetSymbolAddress((void**)&v,    g_v);
    cudaGetSymbolAddress((void**)&attn, g_attn);
    cudaGetSymbolAddress((void**)&y,    g_y);
    cudaGetSymbolAddress((void**)&x1,   g_x1);
    cudaGetSymbolAddress((void**)&x1h,  g_x1h);
    cudaGetSymbolAddress((void**)&hbuf, g_h);
    cudaGetSymbolAddress((void**)&y2,   g_y2);
    cudaGetSymbolAddress((void**)&xh,   g_xh);
    cudaGetSymbolAddress((void**)&wqh,  g_wqh);
    cudaGetSymbolAddress((void**)&wkh,  g_wkh);
    cudaGetSymbolAddress((void**)&wvh,  g_wvh);
    cudaGetSymbolAddress((void**)&wph,  g_wph);
    cudaGetSymbolAddress((void**)&w1h,  g_w1h);
    cudaGetSymbolAddress((void**)&w2h,  g_w2h);

    cudaFuncSetAttribute(attn_kernel,
                         cudaFuncAttributeMaxDynamicSharedMemorySize, ATT_SMEM_BYTES);
    cudaFuncSetAttribute(gemm_h,
                         cudaFuncAttributeMaxDynamicSharedMemorySize, GEMM_SMEM_BYTES);
    cudaFuncSetAttribute(gemm_qkv_h,
                         cudaFuncAttributeMaxDynamicSharedMemorySize, GEMM_SMEM_BYTES);

    dim3 tb(256);
    dim3 gb(128);

    // ---- fused pre-pass (single launch) ----
    prepass_all<<<PP_TOTAL, tb>>>(wq, wk, wv, w_proj, w1, w2, x,
                                  wqh, wkh, wvh, wph, w1h, w2h, xh);

    // fused QKV (z selects matrix) -> half q,k,v
    dim3 gqkv(DMODEL / 128, MTOT / 128, 3);      // (8, 32, 3)
    gemm_qkv_h<<<gqkv, gb, GEMM_SMEM_BYTES>>>(xh, wqh, wkh, wvh, q, k, v);

    // causal attention (longest-first, pipelined K/V) -> half attn
    dim3 ga(SEQ / 64, NH, BATCH);                // (32, 16, 2)
    attn_kernel<<<ga, dim3(128), ATT_SMEM_BYTES>>>(q, k, v, attn);

    // output projection (fp32 C)
    dim3 gq(DMODEL / 128, MTOT / 128);           // (8, 32)
    gemm_h<<<gq, gb, GEMM_SMEM_BYTES>>>(attn, wph, b_proj, y, DMODEL, DMODEL, 0, 0);

    add_ln<<<MTOT, tb>>>(x, y, g1, be1, x1, x1h);

    dim3 gm1(FF / 128, MTOT / 128);              // (32, 32)
    gemm_h<<<gm1, gb, GEMM_SMEM_BYTES>>>(x1h, w1h, b1, hbuf, DMODEL, FF, 1, 1);
    dim3 gm2(DMODEL / 128, MTOT / 128);          // (8, 32)
    gemm_h<<<gm2, gb, GEMM_SMEM_BYTES>>>(hbuf, w2h, b2, y2, FF, DMODEL, 0, 0);

    add_ln<<<MTOT, tb>>>(x1, y2, g2, be2, out, nullptr);
}